// round 1
// baseline (speedup 1.0000x reference)
#include <cuda_runtime.h>
#include <math.h>

// Problem dims (fixed by the dataset)
#define MTOK 8192   // B*S = 4*2048
#define DDIM 1024   // D
#define HDIM 4096   // H
#define NCB  8      // C codebooks
#define KCB  256    // K codes

// Device-global scratch (no allocations allowed in kernel_launch)
__device__ float g_W1[(size_t)HDIM * DDIM];   // [H, D]  row-major
__device__ float g_W2[(size_t)DDIM * HDIM];   // [D, H]  row-major
__device__ float g_h [(size_t)MTOK * HDIM];   // [M, H]  row-major

// ---------------------------------------------------------------------------
// Dequant: W[row, c*sub + j] = cb[c, idx[c, row], j]
// One thread per float4 (sub is a multiple of 4 for both layers).
// ---------------------------------------------------------------------------
__global__ void dequant_kernel(const float* __restrict__ cb,
                               const int*   __restrict__ idx,
                               float* __restrict__ W,
                               int rows, int sub) {
    const int per_row4 = (NCB * sub) >> 2;
    int tid = blockIdx.x * blockDim.x + threadIdx.x;
    if (tid >= rows * per_row4) return;
    int row = tid / per_row4;
    int col = (tid - row * per_row4) << 2;   // float offset within row
    int c   = col / sub;
    int j   = col - c * sub;
    int code = __ldg(&idx[c * rows + row]);
    float4 v = *reinterpret_cast<const float4*>(cb + ((size_t)(c * KCB + code)) * sub + j);
    *reinterpret_cast<float4*>(W + (size_t)row * (NCB * sub) + col) = v;
}

// ---------------------------------------------------------------------------
// NT GEMM: C[m,n] = sum_k A[m,k] * B[n,k]  (both K-major), fused epilogue.
// 128x128 tile, BK=16, 256 threads, 8x8 register tile per thread.
// ---------------------------------------------------------------------------
template<bool GELU>
__global__ __launch_bounds__(256, 2)
void gemm_nt(const float* __restrict__ A, const float* __restrict__ B,
             const float* __restrict__ bias, float* __restrict__ C,
             int M, int N, int K) {
    constexpr int BM = 128, BN = 128, BK = 16;
    __shared__ float As[BK][BM];
    __shared__ float Bs[BK][BN];

    const int t  = threadIdx.x;
    const int tx = t & 15;        // 0..15 -> n sub-tile
    const int ty = t >> 4;        // 0..15 -> m sub-tile
    const int bm = blockIdx.y * BM;
    const int bn = blockIdx.x * BN;

    // Global->shared load mapping: 128 rows x 16 cols = 512 float4; 2 per thread.
    const int lr = t >> 2;          // 0..63 (row within half-tile)
    const int lc = (t & 3) << 2;    // 0,4,8,12 (k offset)
    const float* Ap = A + (size_t)(bm + lr) * K + lc;
    const float* Bp = B + (size_t)(bn + lr) * K + lc;

    float acc[8][8];
    #pragma unroll
    for (int i = 0; i < 8; i++)
        #pragma unroll
        for (int j = 0; j < 8; j++) acc[i][j] = 0.0f;

    for (int k0 = 0; k0 < K; k0 += BK) {
        #pragma unroll
        for (int r = 0; r < 2; r++) {
            float4 a = *reinterpret_cast<const float4*>(Ap + (size_t)(r * 64) * K + k0);
            float4 b = *reinterpret_cast<const float4*>(Bp + (size_t)(r * 64) * K + k0);
            int m = lr + r * 64;
            As[lc + 0][m] = a.x; As[lc + 1][m] = a.y; As[lc + 2][m] = a.z; As[lc + 3][m] = a.w;
            Bs[lc + 0][m] = b.x; Bs[lc + 1][m] = b.y; Bs[lc + 2][m] = b.z; Bs[lc + 3][m] = b.w;
        }
        __syncthreads();

        #pragma unroll
        for (int k = 0; k < BK; k++) {
            float4 a0 = *reinterpret_cast<const float4*>(&As[k][ty * 8]);
            float4 a1 = *reinterpret_cast<const float4*>(&As[k][ty * 8 + 4]);
            float4 b0 = *reinterpret_cast<const float4*>(&Bs[k][tx * 8]);
            float4 b1 = *reinterpret_cast<const float4*>(&Bs[k][tx * 8 + 4]);
            float ra[8] = {a0.x, a0.y, a0.z, a0.w, a1.x, a1.y, a1.z, a1.w};
            float rb[8] = {b0.x, b0.y, b0.z, b0.w, b1.x, b1.y, b1.z, b1.w};
            #pragma unroll
            for (int i = 0; i < 8; i++)
                #pragma unroll
                for (int j = 0; j < 8; j++)
                    acc[i][j] = fmaf(ra[i], rb[j], acc[i][j]);
        }
        __syncthreads();
    }

    // Epilogue: bias (+ exact GELU), vectorized float4 stores.
    #pragma unroll
    for (int i = 0; i < 8; i++) {
        const int m = bm + ty * 8 + i;
        #pragma unroll
        for (int jj = 0; jj < 2; jj++) {
            float4 v;
            float* vp = &v.x;
            #pragma unroll
            for (int q = 0; q < 4; q++) {
                int j = jj * 4 + q;
                int n = bn + tx * 8 + j;
                float xv = acc[i][j] + __ldg(&bias[n]);
                if (GELU) {
                    // exact gelu: 0.5*x*(1+erf(x/sqrt(2)))
                    xv = 0.5f * xv * (1.0f + erff(xv * 0.70710678118654752440f));
                }
                vp[q] = xv;
            }
            *reinterpret_cast<float4*>(C + (size_t)m * N + bn + tx * 8 + jj * 4) = v;
        }
    }
}

// ---------------------------------------------------------------------------
// Launch
// ---------------------------------------------------------------------------
extern "C" void kernel_launch(void* const* d_in, const int* in_sizes, int n_in,
                              void* d_out, int out_size) {
    const float* x    = (const float*)d_in[0];   // [4,2048,1024]
    const float* cb1  = (const float*)d_in[1];   // [8,256,128]
    const int*   idx1 = (const int*)  d_in[2];   // [8,4096]
    const float* b1   = (const float*)d_in[3];   // [4096]
    const float* cb2  = (const float*)d_in[4];   // [8,256,512]
    const int*   idx2 = (const int*)  d_in[5];   // [8,1024]
    const float* b2   = (const float*)d_in[6];   // [1024]
    float* out = (float*)d_out;                  // [4,2048,1024]

    float *W1, *W2, *h;
    cudaGetSymbolAddress((void**)&W1, g_W1);
    cudaGetSymbolAddress((void**)&W2, g_W2);
    cudaGetSymbolAddress((void**)&h,  g_h);

    // Dequant both weight matrices (independent; ~16 MB each)
    {
        int n4 = (HDIM * DDIM) / 4;              // 1M float4
        dequant_kernel<<<(n4 + 255) / 256, 256>>>(cb1, idx1, W1, HDIM, DDIM / NCB);
    }
    {
        int n4 = (DDIM * HDIM) / 4;
        dequant_kernel<<<(n4 + 255) / 256, 256>>>(cb2, idx2, W2, DDIM, HDIM / NCB);
    }

    // GEMM1: h[M,H] = x[M,D] @ W1[H,D]^T + b1, exact GELU
    {
        dim3 grid(HDIM / 128, MTOK / 128);       // (32, 64)
        gemm_nt<true><<<grid, 256>>>(x, W1, b1, h, MTOK, HDIM, DDIM);
    }

    // GEMM2: out[M,D] = h[M,H] @ W2[D,H]^T + b2
    {
        dim3 grid(DDIM / 128, MTOK / 128);       // (8, 64)
        gemm_nt<false><<<grid, 256>>>(h, W2, b2, out, MTOK, DDIM, HDIM);
    }
}

// round 5
// speedup vs baseline: 2.3480x; 2.3480x over previous
#include <cuda_runtime.h>
#include <cuda_bf16.h>
#include <math.h>
#include <stdint.h>

#define MTOK 8192
#define DDIM 1024
#define HDIM 4096
#define NCB  8
#define KCB  256

// hi/lo bf16 operand arrays (static device scratch; no runtime allocation)
__device__ __nv_bfloat16 g_xhi [(size_t)MTOK * DDIM];
__device__ __nv_bfloat16 g_xlo [(size_t)MTOK * DDIM];
__device__ __nv_bfloat16 g_w1hi[(size_t)HDIM * DDIM];
__device__ __nv_bfloat16 g_w1lo[(size_t)HDIM * DDIM];
__device__ __nv_bfloat16 g_w2hi[(size_t)DDIM * HDIM];
__device__ __nv_bfloat16 g_w2lo[(size_t)DDIM * HDIM];
__device__ __nv_bfloat16 g_hhi [(size_t)MTOK * HDIM];
__device__ __nv_bfloat16 g_hlo [(size_t)MTOK * HDIM];

// ---------------------------------------------------------------------------
// asm helpers (all legal on plain compute_103: sm_80-era instructions)
// ---------------------------------------------------------------------------
__device__ __forceinline__ uint32_t smem_u32(const void* p) {
    uint32_t a;
    asm("{ .reg .u64 t; cvta.to.shared.u64 t, %1; cvt.u32.u64 %0, t; }"
        : "=r"(a) : "l"(p));
    return a;
}

#define CP_ASYNC16(dst, src) \
    asm volatile("cp.async.cg.shared.global [%0], [%1], 16;" \
        :: "r"(dst), "l"(src) : "memory")
#define CP_COMMIT() asm volatile("cp.async.commit_group;" ::: "memory")
#define CP_WAIT1()  asm volatile("cp.async.wait_group 1;"  ::: "memory")

#define LDSM_X4(r0, r1, r2, r3, a) \
    asm volatile("ldmatrix.sync.aligned.m8n8.x4.shared.b16 {%0,%1,%2,%3}, [%4];" \
        : "=r"(r0), "=r"(r1), "=r"(r2), "=r"(r3) : "r"(a))

#define MMA_BF16(c, a, b0, b1) \
    asm volatile("mma.sync.aligned.m16n8k16.row.col.f32.bf16.bf16.f32 " \
        "{%0,%1,%2,%3}, {%4,%5,%6,%7}, {%8,%9}, {%0,%1,%2,%3};" \
        : "+f"((c)[0]), "+f"((c)[1]), "+f"((c)[2]), "+f"((c)[3]) \
        : "r"((a)[0]), "r"((a)[1]), "r"((a)[2]), "r"((a)[3]), "r"(b0), "r"(b1))

// ---------------------------------------------------------------------------
// Pre-pass kernels: produce hi/lo bf16 operands
// ---------------------------------------------------------------------------
__device__ __forceinline__ void split4(float4 v, uint32_t& hi0, uint32_t& hi1,
                                       uint32_t& lo0, uint32_t& lo1) {
    __nv_bfloat162 h01 = __floats2bfloat162_rn(v.x, v.y);
    __nv_bfloat162 h23 = __floats2bfloat162_rn(v.z, v.w);
    __nv_bfloat162 l01 = __floats2bfloat162_rn(v.x - __bfloat162float(h01.x),
                                               v.y - __bfloat162float(h01.y));
    __nv_bfloat162 l23 = __floats2bfloat162_rn(v.z - __bfloat162float(h23.x),
                                               v.w - __bfloat162float(h23.y));
    memcpy(&hi0, &h01, 4); memcpy(&hi1, &h23, 4);
    memcpy(&lo0, &l01, 4); memcpy(&lo1, &l23, 4);
}

__global__ void split_x_kernel(const float* __restrict__ x,
                               __nv_bfloat16* __restrict__ xhi,
                               __nv_bfloat16* __restrict__ xlo, int n4) {
    int i = blockIdx.x * blockDim.x + threadIdx.x;
    if (i >= n4) return;
    float4 v = reinterpret_cast<const float4*>(x)[i];
    uint32_t h0, h1, l0, l1;
    split4(v, h0, h1, l0, l1);
    reinterpret_cast<uint2*>(xhi)[i] = make_uint2(h0, h1);
    reinterpret_cast<uint2*>(xlo)[i] = make_uint2(l0, l1);
}

__global__ void dequant_split_kernel(const float* __restrict__ cb,
                                     const int*   __restrict__ idx,
                                     __nv_bfloat16* __restrict__ Whi,
                                     __nv_bfloat16* __restrict__ Wlo,
                                     int rows, int sub) {
    const int per_row4 = (NCB * sub) >> 2;
    int tid = blockIdx.x * blockDim.x + threadIdx.x;
    if (tid >= rows * per_row4) return;
    int row = tid / per_row4;
    int col = (tid - row * per_row4) << 2;
    int c   = col / sub;
    int j   = col - c * sub;
    int code = __ldg(&idx[c * rows + row]);
    float4 v = *reinterpret_cast<const float4*>(cb + ((size_t)(c * KCB + code)) * sub + j);
    uint32_t h0, h1, l0, l1;
    split4(v, h0, h1, l0, l1);
    size_t off = (size_t)row * (NCB * sub) + col;
    *reinterpret_cast<uint2*>(Whi + off) = make_uint2(h0, h1);
    *reinterpret_cast<uint2*>(Wlo + off) = make_uint2(l0, l1);
}

// ---------------------------------------------------------------------------
// Pipelined bf16 mma.sync GEMM, 3-product hi/lo accumulation.
// C[m,n] = sum_k A[m,k]*B[n,k] (+bias, opt GELU). A:[M,K] B:[N,K] bf16 hi/lo.
// CTA 128x128, BK=64, 3 stages, 256 threads (8 warps of 32x64).
// ---------------------------------------------------------------------------
#define BM 128
#define BN 128
#define BKE 64                       // bf16 elements per stage
#define STAGES 3
#define TILE_B  (BM * BKE * 2)       // 16 KB
#define STAGE_B (4 * TILE_B)         // 64 KB: Ahi, Alo, Bhi, Blo
#define SMEM_TOT (STAGES * STAGE_B)  // 192 KB

__device__ __forceinline__ void load_stage(uint32_t stage,
    const __nv_bfloat16* __restrict__ Ahi, const __nv_bfloat16* __restrict__ Alo,
    const __nv_bfloat16* __restrict__ Bhi, const __nv_bfloat16* __restrict__ Blo,
    int bm, int bn, int k0, int K, int tid)
{
    const int row = tid >> 1;            // 0..127
    const int kc0 = (tid & 1) * 4;       // chunk 0..7 (16B each)
    const uint32_t sw = ((uint32_t)(row & 7)) << 4;
    const uint32_t rb = (uint32_t)row * 128;
    const __nv_bfloat16* sA_hi = Ahi + (size_t)(bm + row) * K + k0;
    const __nv_bfloat16* sA_lo = Alo + (size_t)(bm + row) * K + k0;
    const __nv_bfloat16* sB_hi = Bhi + (size_t)(bn + row) * K + k0;
    const __nv_bfloat16* sB_lo = Blo + (size_t)(bn + row) * K + k0;
    #pragma unroll
    for (int i = 0; i < 4; i++) {
        int kc = kc0 + i;
        uint32_t d = stage + rb + (((uint32_t)kc * 16) ^ sw);
        CP_ASYNC16(d + 0 * TILE_B, sA_hi + kc * 8);
        CP_ASYNC16(d + 1 * TILE_B, sA_lo + kc * 8);
        CP_ASYNC16(d + 2 * TILE_B, sB_hi + kc * 8);
        CP_ASYNC16(d + 3 * TILE_B, sB_lo + kc * 8);
    }
}

template<bool GELU, bool OUT_SPLIT>
__global__ __launch_bounds__(256, 1)
void gemm_bf3(const __nv_bfloat16* __restrict__ Ahi, const __nv_bfloat16* __restrict__ Alo,
              const __nv_bfloat16* __restrict__ Bhi, const __nv_bfloat16* __restrict__ Blo,
              const float* __restrict__ bias,
              float* __restrict__ Cf,
              __nv_bfloat16* __restrict__ Chi, __nv_bfloat16* __restrict__ Clo,
              int M, int N, int K)
{
    extern __shared__ __align__(1024) char smem[];
    const uint32_t sb = smem_u32(smem);
    const int tid  = threadIdx.x;
    const int wid  = tid >> 5;
    const int lane = tid & 31;
    const int wr   = wid & 3;          // warp m-tile (32 rows)
    const int wc   = wid >> 2;         // warp n-tile (64 cols)
    const int bm   = blockIdx.y * BM;
    const int bn   = blockIdx.x * BN;

    float acc[2][8][4];
    #pragma unroll
    for (int a = 0; a < 2; a++)
        #pragma unroll
        for (int b = 0; b < 8; b++)
            #pragma unroll
            for (int c = 0; c < 4; c++) acc[a][b][c] = 0.0f;

    // ldmatrix lane addressing (within-tile byte offsets)
    const int amat = lane >> 3, ar = lane & 7;
    const int a_m  = wr * 32 + (amat & 1) * 8 + ar;      // + mt*16 at use
    const uint32_t a_kh = (uint32_t)(amat >> 1) * 16;    // bytes
    const uint32_t a_rb = (uint32_t)a_m * 128;
    const uint32_t a_sx = ((uint32_t)(a_m & 7)) << 4;

    const int bmat = lane >> 3, br = lane & 7;
    const int b_n  = wc * 64 + ((bmat >> 1) << 3) + br;  // + pr*16 at use
    const uint32_t b_kh = (uint32_t)(bmat & 1) * 16;     // bytes
    const uint32_t b_rb = (uint32_t)b_n * 128;
    const uint32_t b_sx = ((uint32_t)(b_n & 7)) << 4;

    const int NT = K / BKE;

    // prologue: prefetch STAGES-1 stages
    #pragma unroll
    for (int s = 0; s < STAGES - 1; s++) {
        load_stage(sb + s * STAGE_B, Ahi, Alo, Bhi, Blo, bm, bn, s * BKE, K, tid);
        CP_COMMIT();
    }

    for (int it = 0; it < NT; it++) {
        CP_WAIT1();
        __syncthreads();

        int pf = it + STAGES - 1;
        if (pf < NT)
            load_stage(sb + (pf % STAGES) * STAGE_B, Ahi, Alo, Bhi, Blo,
                       bm, bn, pf * BKE, K, tid);
        CP_COMMIT();

        const uint32_t st = sb + (it % STAGES) * STAGE_B;
        const uint32_t sAh = st, sAl = st + TILE_B, sBh = st + 2 * TILE_B, sBl = st + 3 * TILE_B;

        #pragma unroll
        for (int kk = 0; kk < 4; kk++) {
            const uint32_t kb = (uint32_t)kk * 32;
            uint32_t ahi[2][4], alo[2][4];
            #pragma unroll
            for (int mt = 0; mt < 2; mt++) {
                uint32_t off = a_rb + mt * 2048 + ((kb + a_kh) ^ a_sx);
                LDSM_X4(ahi[mt][0], ahi[mt][1], ahi[mt][2], ahi[mt][3], sAh + off);
                LDSM_X4(alo[mt][0], alo[mt][1], alo[mt][2], alo[mt][3], sAl + off);
            }
            #pragma unroll
            for (int pr = 0; pr < 4; pr++) {
                uint32_t bhi[4], blo[4];
                uint32_t off = b_rb + pr * 2048 + ((kb + b_kh) ^ b_sx);
                LDSM_X4(bhi[0], bhi[1], bhi[2], bhi[3], sBh + off);
                LDSM_X4(blo[0], blo[1], blo[2], blo[3], sBl + off);
                #pragma unroll
                for (int mt = 0; mt < 2; mt++) {
                    #pragma unroll
                    for (int hf = 0; hf < 2; hf++) {
                        float* c = acc[mt][pr * 2 + hf];
                        MMA_BF16(c, ahi[mt], bhi[hf * 2], bhi[hf * 2 + 1]);
                        MMA_BF16(c, ahi[mt], blo[hf * 2], blo[hf * 2 + 1]);
                        MMA_BF16(c, alo[mt], bhi[hf * 2], bhi[hf * 2 + 1]);
                    }
                }
            }
        }
    }

    // epilogue
    const int mrow = bm + wr * 32 + (lane >> 2);
    const int ncol = bn + wc * 64 + (lane & 3) * 2;
    #pragma unroll
    for (int mt = 0; mt < 2; mt++) {
        #pragma unroll
        for (int n8 = 0; n8 < 8; n8++) {
            const int n = ncol + n8 * 8;
            const float bs0 = __ldg(&bias[n]);
            const float bs1 = __ldg(&bias[n + 1]);
            #pragma unroll
            for (int hf = 0; hf < 2; hf++) {
                const int m = mrow + mt * 16 + hf * 8;
                float v0 = acc[mt][n8][hf * 2 + 0] + bs0;
                float v1 = acc[mt][n8][hf * 2 + 1] + bs1;
                if (GELU) {
                    v0 = 0.5f * v0 * (1.0f + erff(v0 * 0.70710678118654752440f));
                    v1 = 0.5f * v1 * (1.0f + erff(v1 * 0.70710678118654752440f));
                }
                if (OUT_SPLIT) {
                    __nv_bfloat162 h2 = __floats2bfloat162_rn(v0, v1);
                    __nv_bfloat162 l2 = __floats2bfloat162_rn(
                        v0 - __bfloat162float(h2.x), v1 - __bfloat162float(h2.y));
                    *reinterpret_cast<__nv_bfloat162*>(Chi + (size_t)m * N + n) = h2;
                    *reinterpret_cast<__nv_bfloat162*>(Clo + (size_t)m * N + n) = l2;
                } else {
                    *reinterpret_cast<float2*>(Cf + (size_t)m * N + n) = make_float2(v0, v1);
                }
            }
        }
    }
}

// ---------------------------------------------------------------------------
// Launch
// ---------------------------------------------------------------------------
extern "C" void kernel_launch(void* const* d_in, const int* in_sizes, int n_in,
                              void* d_out, int out_size) {
    const float* x    = (const float*)d_in[0];
    const float* cb1  = (const float*)d_in[1];
    const int*   idx1 = (const int*)  d_in[2];
    const float* b1   = (const float*)d_in[3];
    const float* cb2  = (const float*)d_in[4];
    const int*   idx2 = (const int*)  d_in[5];
    const float* b2   = (const float*)d_in[6];
    float* out = (float*)d_out;

    __nv_bfloat16 *xhi, *xlo, *w1hi, *w1lo, *w2hi, *w2lo, *hhi, *hlo;
    cudaGetSymbolAddress((void**)&xhi,  g_xhi);
    cudaGetSymbolAddress((void**)&xlo,  g_xlo);
    cudaGetSymbolAddress((void**)&w1hi, g_w1hi);
    cudaGetSymbolAddress((void**)&w1lo, g_w1lo);
    cudaGetSymbolAddress((void**)&w2hi, g_w2hi);
    cudaGetSymbolAddress((void**)&w2lo, g_w2lo);
    cudaGetSymbolAddress((void**)&hhi,  g_hhi);
    cudaGetSymbolAddress((void**)&hlo,  g_hlo);

    cudaFuncSetAttribute(gemm_bf3<true, true>,
                         cudaFuncAttributeMaxDynamicSharedMemorySize, SMEM_TOT);
    cudaFuncSetAttribute(gemm_bf3<false, false>,
                         cudaFuncAttributeMaxDynamicSharedMemorySize, SMEM_TOT);

    // pre-passes
    {
        int n4 = (MTOK * DDIM) / 4;
        split_x_kernel<<<(n4 + 255) / 256, 256>>>(x, xhi, xlo, n4);
    }
    {
        int n4 = (HDIM * DDIM) / 4;
        dequant_split_kernel<<<(n4 + 255) / 256, 256>>>(cb1, idx1, w1hi, w1lo, HDIM, DDIM / NCB);
    }
    {
        int n4 = (DDIM * HDIM) / 4;
        dequant_split_kernel<<<(n4 + 255) / 256, 256>>>(cb2, idx2, w2hi, w2lo, DDIM, HDIM / NCB);
    }

    // GEMM1: h = gelu(x @ W1^T + b1), written as hi/lo bf16
    {
        dim3 grid(HDIM / BN, MTOK / BM);     // (32, 64)
        gemm_bf3<true, true><<<grid, 256, SMEM_TOT>>>(
            xhi, xlo, w1hi, w1lo, b1, nullptr, hhi, hlo, MTOK, HDIM, DDIM);
    }
    // GEMM2: out = h @ W2^T + b2 (fp32)
    {
        dim3 grid(DDIM / BN, MTOK / BM);     // (8, 64)
        gemm_bf3<false, false><<<grid, 256, SMEM_TOT>>>(
            hhi, hlo, w2hi, w2lo, b2, out, nullptr, nullptr, MTOK, DDIM, HDIM);
    }
}

// round 6
// speedup vs baseline: 2.6386x; 1.1238x over previous
#include <cuda_runtime.h>
#include <cuda_bf16.h>
#include <math.h>
#include <stdint.h>

#define MTOK 8192
#define DDIM 1024
#define HDIM 4096
#define NCB  8
#define KCB  256

__device__ __nv_bfloat16 g_xhi [(size_t)MTOK * DDIM];
__device__ __nv_bfloat16 g_xlo [(size_t)MTOK * DDIM];
__device__ __nv_bfloat16 g_w1hi[(size_t)HDIM * DDIM];
__device__ __nv_bfloat16 g_w1lo[(size_t)HDIM * DDIM];
__device__ __nv_bfloat16 g_w2hi[(size_t)DDIM * HDIM];
__device__ __nv_bfloat16 g_w2lo[(size_t)DDIM * HDIM];
__device__ __nv_bfloat16 g_hhi [(size_t)MTOK * HDIM];
__device__ __nv_bfloat16 g_hlo [(size_t)MTOK * HDIM];

// ---------------------------------------------------------------------------
__device__ __forceinline__ uint32_t smem_u32(const void* p) {
    uint32_t a;
    asm("{ .reg .u64 t; cvta.to.shared.u64 t, %1; cvt.u32.u64 %0, t; }"
        : "=r"(a) : "l"(p));
    return a;
}

#define CP_ASYNC16(dst, src) \
    asm volatile("cp.async.cg.shared.global [%0], [%1], 16;" \
        :: "r"(dst), "l"(src) : "memory")
#define CP_COMMIT() asm volatile("cp.async.commit_group;" ::: "memory")
#define CP_WAIT0()  asm volatile("cp.async.wait_group 0;"  ::: "memory")

#define LDSM_X4(r0, r1, r2, r3, a) \
    asm volatile("ldmatrix.sync.aligned.m8n8.x4.shared.b16 {%0,%1,%2,%3}, [%4];" \
        : "=r"(r0), "=r"(r1), "=r"(r2), "=r"(r3) : "r"(a))

#define MMA_BF16(c, a, b0, b1) \
    asm volatile("mma.sync.aligned.m16n8k16.row.col.f32.bf16.bf16.f32 " \
        "{%0,%1,%2,%3}, {%4,%5,%6,%7}, {%8,%9}, {%0,%1,%2,%3};" \
        : "+f"((c)[0]), "+f"((c)[1]), "+f"((c)[2]), "+f"((c)[3]) \
        : "r"((a)[0]), "r"((a)[1]), "r"((a)[2]), "r"((a)[3]), "r"(b0), "r"(b1))

// ---------------------------------------------------------------------------
// Pre-pass kernels
// ---------------------------------------------------------------------------
__device__ __forceinline__ void split4(float4 v, uint32_t& hi0, uint32_t& hi1,
                                       uint32_t& lo0, uint32_t& lo1) {
    __nv_bfloat162 h01 = __floats2bfloat162_rn(v.x, v.y);
    __nv_bfloat162 h23 = __floats2bfloat162_rn(v.z, v.w);
    __nv_bfloat162 l01 = __floats2bfloat162_rn(v.x - __bfloat162float(h01.x),
                                               v.y - __bfloat162float(h01.y));
    __nv_bfloat162 l23 = __floats2bfloat162_rn(v.z - __bfloat162float(h23.x),
                                               v.w - __bfloat162float(h23.y));
    memcpy(&hi0, &h01, 4); memcpy(&hi1, &h23, 4);
    memcpy(&lo0, &l01, 4); memcpy(&lo1, &l23, 4);
}

__global__ void split_x_kernel(const float* __restrict__ x,
                               __nv_bfloat16* __restrict__ xhi,
                               __nv_bfloat16* __restrict__ xlo, int n4) {
    int i = blockIdx.x * blockDim.x + threadIdx.x;
    if (i >= n4) return;
    float4 v = reinterpret_cast<const float4*>(x)[i];
    uint32_t h0, h1, l0, l1;
    split4(v, h0, h1, l0, l1);
    reinterpret_cast<uint2*>(xhi)[i] = make_uint2(h0, h1);
    reinterpret_cast<uint2*>(xlo)[i] = make_uint2(l0, l1);
}

__global__ void dequant_split_kernel(const float* __restrict__ cb,
                                     const int*   __restrict__ idx,
                                     __nv_bfloat16* __restrict__ Whi,
                                     __nv_bfloat16* __restrict__ Wlo,
                                     int rows, int sub) {
    const int per_row4 = (NCB * sub) >> 2;
    int tid = blockIdx.x * blockDim.x + threadIdx.x;
    if (tid >= rows * per_row4) return;
    int row = tid / per_row4;
    int col = (tid - row * per_row4) << 2;
    int c   = col / sub;
    int j   = col - c * sub;
    int code = __ldg(&idx[c * rows + row]);
    float4 v = *reinterpret_cast<const float4*>(cb + ((size_t)(c * KCB + code)) * sub + j);
    uint32_t h0, h1, l0, l1;
    split4(v, h0, h1, l0, l1);
    size_t off = (size_t)row * (NCB * sub) + col;
    *reinterpret_cast<uint2*>(Whi + off) = make_uint2(h0, h1);
    *reinterpret_cast<uint2*>(Wlo + off) = make_uint2(l0, l1);
}

// ---------------------------------------------------------------------------
// Pipelined bf16 mma.sync GEMM, 3-product hi/lo accumulation.
// CTA tile 128x256, BK=64, 2-stage double buffer, 256 threads.
// 8 warps in 2(m) x 4(n); warp tile 64x64.
// ---------------------------------------------------------------------------
#define BM 128
#define BN 256
#define BKE 64
#define TILE_A  (BM * BKE * 2)                 // 16 KB
#define TILE_BB (BN * BKE * 2)                 // 32 KB
#define STAGE_B (2 * TILE_A + 2 * TILE_BB)     // 96 KB
#define SMEM_TOT (2 * STAGE_B)                 // 192 KB

__device__ __forceinline__ void load_stage(uint32_t stage,
    const __nv_bfloat16* __restrict__ Ahi, const __nv_bfloat16* __restrict__ Alo,
    const __nv_bfloat16* __restrict__ Bhi, const __nv_bfloat16* __restrict__ Blo,
    int bm, int bn, int k0, int K, int tid)
{
    const int row = tid >> 1;            // 0..127
    const int kc0 = (tid & 1) * 4;       // 16B-chunk 0..7
    const uint32_t sw  = ((uint32_t)(row & 7)) << 4;
    const uint32_t rb  = (uint32_t)row * 128;
    const uint32_t sAh = stage;
    const uint32_t sAl = stage + TILE_A;
    const uint32_t sBh = stage + 2 * TILE_A;
    const uint32_t sBl = stage + 2 * TILE_A + TILE_BB;

    const __nv_bfloat16* pAh = Ahi + (size_t)(bm + row) * K + k0;
    const __nv_bfloat16* pAl = Alo + (size_t)(bm + row) * K + k0;
    #pragma unroll
    for (int i = 0; i < 4; i++) {
        int kc = kc0 + i;
        uint32_t d = rb + (((uint32_t)kc * 16) ^ sw);
        CP_ASYNC16(sAh + d, pAh + kc * 8);
        CP_ASYNC16(sAl + d, pAl + kc * 8);
    }
    #pragma unroll
    for (int g = 0; g < 2; g++) {
        int brow = row + g * 128;
        const __nv_bfloat16* pBh = Bhi + (size_t)(bn + brow) * K + k0;
        const __nv_bfloat16* pBl = Blo + (size_t)(bn + brow) * K + k0;
        uint32_t brb = (uint32_t)brow * 128;
        #pragma unroll
        for (int i = 0; i < 4; i++) {
            int kc = kc0 + i;
            uint32_t d = brb + (((uint32_t)kc * 16) ^ sw);
            CP_ASYNC16(sBh + d, pBh + kc * 8);
            CP_ASYNC16(sBl + d, pBl + kc * 8);
        }
    }
}

template<bool GELU, bool OUT_SPLIT>
__global__ __launch_bounds__(256, 1)
void gemm_bf3(const __nv_bfloat16* __restrict__ Ahi, const __nv_bfloat16* __restrict__ Alo,
              const __nv_bfloat16* __restrict__ Bhi, const __nv_bfloat16* __restrict__ Blo,
              const float* __restrict__ bias,
              float* __restrict__ Cf,
              __nv_bfloat16* __restrict__ Chi, __nv_bfloat16* __restrict__ Clo,
              int M, int N, int K)
{
    extern __shared__ __align__(1024) char smem[];
    const uint32_t sb = smem_u32(smem);
    const int tid  = threadIdx.x;
    const int wid  = tid >> 5;
    const int lane = tid & 31;
    const int wr   = wid & 1;          // warp m-tile (64 rows)
    const int wc   = wid >> 1;         // warp n-tile (64 cols)
    const int bm   = blockIdx.y * BM;
    const int bn   = blockIdx.x * BN;

    float acc[4][8][4];                // [mt][pr*2+hf][4]
    #pragma unroll
    for (int a = 0; a < 4; a++)
        #pragma unroll
        for (int b = 0; b < 8; b++)
            #pragma unroll
            for (int c = 0; c < 4; c++) acc[a][b][c] = 0.0f;

    // ldmatrix lane addressing
    const int amat = lane >> 3, ar = lane & 7;
    const int a_m  = wr * 64 + (amat & 1) * 8 + ar;      // + mt*16
    const uint32_t a_kh = (uint32_t)(amat >> 1) * 16;
    const uint32_t a_rb = (uint32_t)a_m * 128;
    const uint32_t a_sx = ((uint32_t)(a_m & 7)) << 4;

    const int bmat = lane >> 3, br = lane & 7;
    const int b_n  = wc * 64 + ((bmat >> 1) << 3) + br;  // + pr*16
    const uint32_t b_kh = (uint32_t)(bmat & 1) * 16;
    const uint32_t b_rb = (uint32_t)b_n * 128;
    const uint32_t b_sx = ((uint32_t)(b_n & 7)) << 4;

    const int NT = K / BKE;

    // prologue: prefetch stage 0
    load_stage(sb, Ahi, Alo, Bhi, Blo, bm, bn, 0, K, tid);
    CP_COMMIT();

    for (int it = 0; it < NT; it++) {
        CP_WAIT0();
        __syncthreads();

        int pf = it + 1;
        if (pf < NT) {
            load_stage(sb + (pf & 1) * STAGE_B, Ahi, Alo, Bhi, Blo,
                       bm, bn, pf * BKE, K, tid);
            CP_COMMIT();
        }

        const uint32_t st  = sb + (it & 1) * STAGE_B;
        const uint32_t sAh = st;
        const uint32_t sAl = st + TILE_A;
        const uint32_t sBh = st + 2 * TILE_A;
        const uint32_t sBl = st + 2 * TILE_A + TILE_BB;

        #pragma unroll
        for (int kk = 0; kk < 4; kk++) {
            const uint32_t kb = (uint32_t)kk * 32;
            uint32_t ahi[4][4], alo[4][4];
            #pragma unroll
            for (int mt = 0; mt < 4; mt++) {
                uint32_t off = a_rb + mt * 2048 + ((kb + a_kh) ^ a_sx);
                LDSM_X4(ahi[mt][0], ahi[mt][1], ahi[mt][2], ahi[mt][3], sAh + off);
                LDSM_X4(alo[mt][0], alo[mt][1], alo[mt][2], alo[mt][3], sAl + off);
            }
            #pragma unroll
            for (int pr = 0; pr < 4; pr++) {
                uint32_t bhi[4], blo[4];
                uint32_t off = b_rb + pr * 2048 + ((kb + b_kh) ^ b_sx);
                LDSM_X4(bhi[0], bhi[1], bhi[2], bhi[3], sBh + off);
                LDSM_X4(blo[0], blo[1], blo[2], blo[3], sBl + off);
                // de-chained order: all hi*hi, then hi*lo, then lo*hi
                #pragma unroll
                for (int mt = 0; mt < 4; mt++) {
                    MMA_BF16(acc[mt][pr * 2 + 0], ahi[mt], bhi[0], bhi[1]);
                    MMA_BF16(acc[mt][pr * 2 + 1], ahi[mt], bhi[2], bhi[3]);
                }
                #pragma unroll
                for (int mt = 0; mt < 4; mt++) {
                    MMA_BF16(acc[mt][pr * 2 + 0], ahi[mt], blo[0], blo[1]);
                    MMA_BF16(acc[mt][pr * 2 + 1], ahi[mt], blo[2], blo[3]);
                }
                #pragma unroll
                for (int mt = 0; mt < 4; mt++) {
                    MMA_BF16(acc[mt][pr * 2 + 0], alo[mt], bhi[0], bhi[1]);
                    MMA_BF16(acc[mt][pr * 2 + 1], alo[mt], bhi[2], bhi[3]);
                }
            }
        }
    }

    // epilogue
    const int mrow = bm + wr * 64 + (lane >> 2);
    const int ncol = bn + wc * 64 + (lane & 3) * 2;
    #pragma unroll
    for (int mt = 0; mt < 4; mt++) {
        #pragma unroll
        for (int n8 = 0; n8 < 8; n8++) {
            const int n = ncol + n8 * 8;
            const float bs0 = __ldg(&bias[n]);
            const float bs1 = __ldg(&bias[n + 1]);
            #pragma unroll
            for (int hf = 0; hf < 2; hf++) {
                const int m = mrow + mt * 16 + hf * 8;
                float v0 = acc[mt][n8][hf * 2 + 0] + bs0;
                float v1 = acc[mt][n8][hf * 2 + 1] + bs1;
                if (GELU) {
                    v0 = 0.5f * v0 * (1.0f + erff(v0 * 0.70710678118654752440f));
                    v1 = 0.5f * v1 * (1.0f + erff(v1 * 0.70710678118654752440f));
                }
                if (OUT_SPLIT) {
                    __nv_bfloat162 h2 = __floats2bfloat162_rn(v0, v1);
                    __nv_bfloat162 l2 = __floats2bfloat162_rn(
                        v0 - __bfloat162float(h2.x), v1 - __bfloat162float(h2.y));
                    *reinterpret_cast<__nv_bfloat162*>(Chi + (size_t)m * N + n) = h2;
                    *reinterpret_cast<__nv_bfloat162*>(Clo + (size_t)m * N + n) = l2;
                } else {
                    *reinterpret_cast<float2*>(Cf + (size_t)m * N + n) = make_float2(v0, v1);
                }
            }
        }
    }
}

// ---------------------------------------------------------------------------
extern "C" void kernel_launch(void* const* d_in, const int* in_sizes, int n_in,
                              void* d_out, int out_size) {
    const float* x    = (const float*)d_in[0];
    const float* cb1  = (const float*)d_in[1];
    const int*   idx1 = (const int*)  d_in[2];
    const float* b1   = (const float*)d_in[3];
    const float* cb2  = (const float*)d_in[4];
    const int*   idx2 = (const int*)  d_in[5];
    const float* b2   = (const float*)d_in[6];
    float* out = (float*)d_out;

    __nv_bfloat16 *xhi, *xlo, *w1hi, *w1lo, *w2hi, *w2lo, *hhi, *hlo;
    cudaGetSymbolAddress((void**)&xhi,  g_xhi);
    cudaGetSymbolAddress((void**)&xlo,  g_xlo);
    cudaGetSymbolAddress((void**)&w1hi, g_w1hi);
    cudaGetSymbolAddress((void**)&w1lo, g_w1lo);
    cudaGetSymbolAddress((void**)&w2hi, g_w2hi);
    cudaGetSymbolAddress((void**)&w2lo, g_w2lo);
    cudaGetSymbolAddress((void**)&hhi,  g_hhi);
    cudaGetSymbolAddress((void**)&hlo,  g_hlo);

    cudaFuncSetAttribute(gemm_bf3<true, true>,
                         cudaFuncAttributeMaxDynamicSharedMemorySize, SMEM_TOT);
    cudaFuncSetAttribute(gemm_bf3<false, false>,
                         cudaFuncAttributeMaxDynamicSharedMemorySize, SMEM_TOT);

    {
        int n4 = (MTOK * DDIM) / 4;
        split_x_kernel<<<(n4 + 255) / 256, 256>>>(x, xhi, xlo, n4);
    }
    {
        int n4 = (HDIM * DDIM) / 4;
        dequant_split_kernel<<<(n4 + 255) / 256, 256>>>(cb1, idx1, w1hi, w1lo, HDIM, DDIM / NCB);
    }
    {
        int n4 = (DDIM * HDIM) / 4;
        dequant_split_kernel<<<(n4 + 255) / 256, 256>>>(cb2, idx2, w2hi, w2lo, DDIM, HDIM / NCB);
    }

    {
        dim3 grid(HDIM / BN, MTOK / BM);     // (16, 64)
        gemm_bf3<true, true><<<grid, 256, SMEM_TOT>>>(
            xhi, xlo, w1hi, w1lo, b1, nullptr, hhi, hlo, MTOK, HDIM, DDIM);
    }
    {
        dim3 grid(DDIM / BN, MTOK / BM);     // (4, 64)
        gemm_bf3<false, false><<<grid, 256, SMEM_TOT>>>(
            hhi, hlo, w2hi, w2lo, b2, out, nullptr, nullptr, MTOK, DDIM, HDIM);
    }
}